// round 1
// baseline (speedup 1.0000x reference)
#include <cuda_runtime.h>
#include <math.h>
#include <float.h>

#define BB 4
#define NN 2048
#define DD 1024
#define RR 64
#define LN_EPS 1e-5f
#define NTOK (BB*NN)

// ---------------- scratch (no allocations allowed) ----------------
__device__ float g_Q[NTOK * RR];                      // 2 MB
__device__ float g_K[NTOK * RR];                      // 2 MB
__device__ float g_inv[NTOK];                         // 32 KB
__device__ float g_S[(size_t)BB * NN * NN];           // 64 MB (scores -> probs)
__device__ float g_delta[(size_t)BB * NN * DD];       // 32 MB

// ---------------- 1/sqrt(max(sum(mask),1)) per token ----------------
__global__ void reff_kernel(const float* __restrict__ mask) {
    int t = blockIdx.x * blockDim.x + threadIdx.x;
    if (t >= NTOK) return;
    const float4* m = (const float4*)(mask + (size_t)t * RR);
    float s = 0.f;
#pragma unroll
    for (int i = 0; i < RR / 4; i++) {
        float4 v = m[i];
        s += v.x + v.y + v.z + v.w;
    }
    g_inv[t] = rsqrtf(fmaxf(s, 1.0f));
}

// ---------------- Q/K projection: [8192,1024] @ [1024,128] with mask gate ----
// BM=64 tokens, BN=128 (Q cols 0..63 | K cols 64..127), BK=16, 256 thr, 4x8 tile
__global__ __launch_bounds__(256) void proj_kernel(
    const float* __restrict__ x, const float* __restrict__ mask,
    const float* __restrict__ U, const float* __restrict__ Vw) {
    __shared__ float xs[16][64 + 1];   // [k][m]
    __shared__ float ws[16][128];      // [k][c]
    int m0 = blockIdx.x * 64;
    int tid = threadIdx.x;
    int ty = tid / 16, tx = tid % 16;  // rows ty*4.., cols tx*8..
    float acc[4][8] = {};
    for (int k0 = 0; k0 < DD; k0 += 16) {
        {   // x tile, transposed
            int i = tid >> 2;
            int j = (tid & 3) * 4;
            float4 v = *(const float4*)(x + (size_t)(m0 + i) * DD + k0 + j);
            xs[j + 0][i] = v.x; xs[j + 1][i] = v.y;
            xs[j + 2][i] = v.z; xs[j + 3][i] = v.w;
        }
        {   // weight tile (U|V concat)
            int j = tid >> 4;
            int c0 = (tid & 15) * 8;
            const float* src = (c0 < 64) ? (U + (size_t)(k0 + j) * RR + c0)
                                         : (Vw + (size_t)(k0 + j) * RR + (c0 - 64));
            *(float4*)&ws[j][c0]     = *(const float4*)(src);
            *(float4*)&ws[j][c0 + 4] = *(const float4*)(src + 4);
        }
        __syncthreads();
#pragma unroll
        for (int k = 0; k < 16; k++) {
            float a[4], b[8];
#pragma unroll
            for (int i = 0; i < 4; i++) a[i] = xs[k][ty * 4 + i];
#pragma unroll
            for (int j = 0; j < 8; j++) b[j] = ws[k][tx * 8 + j];
#pragma unroll
            for (int i = 0; i < 4; i++)
#pragma unroll
                for (int j = 0; j < 8; j++) acc[i][j] += a[i] * b[j];
        }
        __syncthreads();
    }
#pragma unroll
    for (int i = 0; i < 4; i++) {
        int token = m0 + ty * 4 + i;
#pragma unroll
        for (int j = 0; j < 8; j++) {
            int c = tx * 8 + j;
            if (c < 64) {
                float mm = mask[(size_t)token * RR + c];
                g_Q[(size_t)token * RR + c] = acc[i][j] * mm;
            } else {
                int r = c - 64;
                float mm = mask[(size_t)token * RR + r];
                g_K[(size_t)token * RR + r] = acc[i][j] * mm;
            }
        }
    }
}

// ---------------- scores: S[b,q,k] = (Q[q,:].K[k,:]) * inv[q] -----------------
// 64x64 output tile, full R=64 in smem, 4x4 thread tile, 256 threads
__global__ __launch_bounds__(256) void scores_kernel() {
    __shared__ float Qs[64][RR + 1];
    __shared__ float Ks[64][RR + 1];
    int b  = blockIdx.z;
    int q0 = blockIdx.y * 64;
    int k0 = blockIdx.x * 64;
    int tid = threadIdx.x;
    {
        int i  = tid >> 2;
        int r0 = (tid & 3) * 16;
        const float* qp = g_Q + ((size_t)b * NN + q0 + i) * RR + r0;
        const float* kp = g_K + ((size_t)b * NN + k0 + i) * RR + r0;
#pragma unroll
        for (int c = 0; c < 4; c++) {
            float4 v = *(const float4*)(qp + c * 4);
            Qs[i][r0 + c * 4 + 0] = v.x; Qs[i][r0 + c * 4 + 1] = v.y;
            Qs[i][r0 + c * 4 + 2] = v.z; Qs[i][r0 + c * 4 + 3] = v.w;
            float4 w = *(const float4*)(kp + c * 4);
            Ks[i][r0 + c * 4 + 0] = w.x; Ks[i][r0 + c * 4 + 1] = w.y;
            Ks[i][r0 + c * 4 + 2] = w.z; Ks[i][r0 + c * 4 + 3] = w.w;
        }
    }
    __syncthreads();
    int ty = tid / 16, tx = tid % 16;
    float acc[4][4] = {};
#pragma unroll 8
    for (int r = 0; r < RR; r++) {
        float a[4], bv[4];
#pragma unroll
        for (int i = 0; i < 4; i++) a[i]  = Qs[ty * 4 + i][r];
#pragma unroll
        for (int j = 0; j < 4; j++) bv[j] = Ks[tx * 4 + j][r];
#pragma unroll
        for (int i = 0; i < 4; i++)
#pragma unroll
            for (int j = 0; j < 4; j++) acc[i][j] += a[i] * bv[j];
    }
    float* Sb = g_S + (size_t)b * NN * NN;
#pragma unroll
    for (int i = 0; i < 4; i++) {
        int q = q0 + ty * 4 + i;
        float inv = g_inv[b * NN + q];
        float4 o;
        o.x = acc[i][0] * inv; o.y = acc[i][1] * inv;
        o.z = acc[i][2] * inv; o.w = acc[i][3] * inv;
        *(float4*)(Sb + (size_t)q * NN + k0 + tx * 4) = o;
    }
}

// ---------------- softmax over rows of S (len 2048), in place ----------------
__global__ __launch_bounds__(256) void softmax_kernel() {
    __shared__ float red[8];
    size_t row = blockIdx.x;
    float* S = g_S + row * NN;
    int tid = threadIdx.x;
    float v[8];
    float4 a = *(const float4*)(S + tid * 8);
    float4 b = *(const float4*)(S + tid * 8 + 4);
    v[0] = a.x; v[1] = a.y; v[2] = a.z; v[3] = a.w;
    v[4] = b.x; v[5] = b.y; v[6] = b.z; v[7] = b.w;
    float m = -FLT_MAX;
#pragma unroll
    for (int i = 0; i < 8; i++) m = fmaxf(m, v[i]);
#pragma unroll
    for (int o = 16; o > 0; o >>= 1) m = fmaxf(m, __shfl_xor_sync(0xffffffffu, m, o));
    if ((tid & 31) == 0) red[tid >> 5] = m;
    __syncthreads();
    if (tid < 32) {
        float t = (tid < 8) ? red[tid] : -FLT_MAX;
#pragma unroll
        for (int o = 4; o > 0; o >>= 1) t = fmaxf(t, __shfl_xor_sync(0xffffffffu, t, o));
        if (tid == 0) red[0] = t;
    }
    __syncthreads();
    m = red[0];
    __syncthreads();
    float s = 0.f;
#pragma unroll
    for (int i = 0; i < 8; i++) { v[i] = __expf(v[i] - m); s += v[i]; }
#pragma unroll
    for (int o = 16; o > 0; o >>= 1) s += __shfl_xor_sync(0xffffffffu, s, o);
    if ((tid & 31) == 0) red[tid >> 5] = s;
    __syncthreads();
    if (tid < 32) {
        float t = (tid < 8) ? red[tid] : 0.f;
#pragma unroll
        for (int o = 4; o > 0; o >>= 1) t += __shfl_xor_sync(0xffffffffu, t, o);
        if (tid == 0) red[0] = t;
    }
    __syncthreads();
    float w = 1.0f / red[0];
    float4 oa, ob;
    oa.x = v[0] * w; oa.y = v[1] * w; oa.z = v[2] * w; oa.w = v[3] * w;
    ob.x = v[4] * w; ob.y = v[5] * w; ob.z = v[6] * w; ob.w = v[7] * w;
    *(float4*)(S + tid * 8)     = oa;
    *(float4*)(S + tid * 8 + 4) = ob;
}

// ---------------- delta = P @ x : per-batch 2048x1024x2048 sgemm -------------
// BM=128 (q), BN=128 (d), BK=16, 256 threads, 8x8 microtile
__global__ __launch_bounds__(256) void delta_kernel(const float* __restrict__ x) {
    __shared__ float Pt[16][128];   // [k][q]
    __shared__ float xs[16][128];   // [k][d]
    int b  = blockIdx.z;
    int q0 = blockIdx.y * 128;
    int d0 = blockIdx.x * 128;
    const float* Sb = g_S + (size_t)b * NN * NN;
    const float* xb = x + (size_t)b * NN * DD;
    int tid = threadIdx.x;
    int ty = tid / 16, tx = tid % 16;
    float acc[8][8] = {};
    for (int k0 = 0; k0 < NN; k0 += 16) {
        {   // P tile, transposed
            int i  = tid >> 1;
            int j0 = (tid & 1) * 8;
            const float* p = Sb + (size_t)(q0 + i) * NN + k0 + j0;
            float4 v0 = *(const float4*)p;
            float4 v1 = *(const float4*)(p + 4);
            Pt[j0 + 0][i] = v0.x; Pt[j0 + 1][i] = v0.y;
            Pt[j0 + 2][i] = v0.z; Pt[j0 + 3][i] = v0.w;
            Pt[j0 + 4][i] = v1.x; Pt[j0 + 5][i] = v1.y;
            Pt[j0 + 6][i] = v1.z; Pt[j0 + 7][i] = v1.w;
        }
        {   // x tile
            int j  = tid >> 4;
            int i0 = (tid & 15) * 8;
            const float* p = xb + (size_t)(k0 + j) * DD + d0 + i0;
            *(float4*)&xs[j][i0]     = *(const float4*)p;
            *(float4*)&xs[j][i0 + 4] = *(const float4*)(p + 4);
        }
        __syncthreads();
#pragma unroll
        for (int k = 0; k < 16; k++) {
            float a[8], bv[8];
            *(float4*)(a)      = *(float4*)&Pt[k][ty * 8];
            *(float4*)(a + 4)  = *(float4*)&Pt[k][ty * 8 + 4];
            *(float4*)(bv)     = *(float4*)&xs[k][tx * 8];
            *(float4*)(bv + 4) = *(float4*)&xs[k][tx * 8 + 4];
#pragma unroll
            for (int i = 0; i < 8; i++)
#pragma unroll
                for (int j = 0; j < 8; j++) acc[i][j] += a[i] * bv[j];
        }
        __syncthreads();
    }
    float* dp = g_delta + ((size_t)b * NN + q0) * DD + d0;
#pragma unroll
    for (int i = 0; i < 8; i++) {
        int row = ty * 8 + i;
        float4 o0, o1;
        o0.x = acc[i][0]; o0.y = acc[i][1]; o0.z = acc[i][2]; o0.w = acc[i][3];
        o1.x = acc[i][4]; o1.y = acc[i][5]; o1.z = acc[i][6]; o1.w = acc[i][7];
        *(float4*)(dp + (size_t)row * DD + tx * 8)     = o0;
        *(float4*)(dp + (size_t)row * DD + tx * 8 + 4) = o1;
    }
}

// ---------------- out = LN(x + delta) ----------------------------------------
__global__ __launch_bounds__(256) void ln_kernel(
    const float* __restrict__ x, const float* __restrict__ gamma,
    const float* __restrict__ beta, float* __restrict__ out) {
    __shared__ float red[8];
    size_t token = blockIdx.x;
    const float* xr = x + token * DD;
    const float* dr = g_delta + token * DD;
    int tid = threadIdx.x;
    float4 xv = *(const float4*)(xr + tid * 4);
    float4 dv = *(const float4*)(dr + tid * 4);
    float y[4] = {xv.x + dv.x, xv.y + dv.y, xv.z + dv.z, xv.w + dv.w};
    float s = y[0] + y[1] + y[2] + y[3];
#pragma unroll
    for (int o = 16; o > 0; o >>= 1) s += __shfl_xor_sync(0xffffffffu, s, o);
    if ((tid & 31) == 0) red[tid >> 5] = s;
    __syncthreads();
    if (tid < 32) {
        float t = (tid < 8) ? red[tid] : 0.f;
#pragma unroll
        for (int o = 4; o > 0; o >>= 1) t += __shfl_xor_sync(0xffffffffu, t, o);
        if (tid == 0) red[0] = t;
    }
    __syncthreads();
    float mu = red[0] * (1.0f / DD);
    __syncthreads();
    float vs = 0.f;
#pragma unroll
    for (int i = 0; i < 4; i++) { float d = y[i] - mu; vs += d * d; }
#pragma unroll
    for (int o = 16; o > 0; o >>= 1) vs += __shfl_xor_sync(0xffffffffu, vs, o);
    if ((tid & 31) == 0) red[tid >> 5] = vs;
    __syncthreads();
    if (tid < 32) {
        float t = (tid < 8) ? red[tid] : 0.f;
#pragma unroll
        for (int o = 4; o > 0; o >>= 1) t += __shfl_xor_sync(0xffffffffu, t, o);
        if (tid == 0) red[0] = t;
    }
    __syncthreads();
    float inv = rsqrtf(red[0] * (1.0f / DD) + LN_EPS);
    float4 gv = *(const float4*)(gamma + tid * 4);
    float4 bv = *(const float4*)(beta + tid * 4);
    float4 o;
    o.x = (y[0] - mu) * inv * gv.x + bv.x;
    o.y = (y[1] - mu) * inv * gv.y + bv.y;
    o.z = (y[2] - mu) * inv * gv.z + bv.z;
    o.w = (y[3] - mu) * inv * gv.w + bv.w;
    *(float4*)(out + token * DD + tid * 4) = o;
}

extern "C" void kernel_launch(void* const* d_in, const int* in_sizes, int n_in,
                              void* d_out, int out_size) {
    const float* x     = (const float*)d_in[0];
    const float* mask  = (const float*)d_in[1];
    const float* U     = (const float*)d_in[2];
    const float* Vw    = (const float*)d_in[3];
    const float* gamma = (const float*)d_in[4];
    const float* beta  = (const float*)d_in[5];
    float* out = (float*)d_out;

    reff_kernel<<<(NTOK + 255) / 256, 256>>>(mask);
    proj_kernel<<<NTOK / 64, 256>>>(x, mask, U, Vw);
    scores_kernel<<<dim3(NN / 64, NN / 64, BB), 256>>>();
    softmax_kernel<<<NTOK, 256>>>();
    delta_kernel<<<dim3(DD / 128, NN / 128, BB), 256>>>(x);
    ln_kernel<<<NTOK, 256>>>(x, gamma, beta, out);
}

// round 4
// speedup vs baseline: 3.6650x; 3.6650x over previous
#include <cuda_runtime.h>
#include <cuda_fp16.h>
#include <math.h>
#include <float.h>
#include <stdint.h>

#define BB 4
#define NN 2048
#define DD 1024
#define RR 64
#define LN_EPS 1e-5f
#define NTOK (BB*NN)

// ---------------- scratch (no allocations allowed) ----------------
__device__ __half g_Qh[NTOK * RR];                    // 1 MB
__device__ __half g_Kh[NTOK * RR];                    // 1 MB
__device__ float  g_inv[NTOK];                        // 32 KB
__device__ float  g_S[(size_t)BB * NN * NN];          // 64 MB scores (fp32)
__device__ __half g_Ph[(size_t)BB * NN * NN];         // 32 MB probs  (fp16)
__device__ __half g_xt[(size_t)BB * DD * NN];         // 16 MB x^T    (fp16)
__device__ float  g_delta[(size_t)BB * NN * DD];      // 32 MB

// ================= warp-mma helpers (sm_80+ path, legal on compute_103) =====
__device__ __forceinline__ uint32_t smem_u32(const void* p) {
    uint32_t a;
    asm("{ .reg .u64 t; cvta.to.shared.u64 t, %1; cvt.u32.u64 %0, t; }" : "=r"(a) : "l"(p));
    return a;
}
__device__ __forceinline__ void ldsm_x4(uint32_t& r0, uint32_t& r1, uint32_t& r2,
                                        uint32_t& r3, uint32_t addr) {
    asm volatile("ldmatrix.sync.aligned.m8n8.x4.shared.b16 {%0,%1,%2,%3}, [%4];"
                 : "=r"(r0), "=r"(r1), "=r"(r2), "=r"(r3) : "r"(addr));
}
__device__ __forceinline__ void mma16816(float* c, const uint32_t* a,
                                         uint32_t b0, uint32_t b1) {
    asm volatile("mma.sync.aligned.m16n8k16.row.col.f32.f16.f16.f32 "
                 "{%0,%1,%2,%3}, {%4,%5,%6,%7}, {%8,%9}, {%0,%1,%2,%3};"
                 : "+f"(c[0]), "+f"(c[1]), "+f"(c[2]), "+f"(c[3])
                 : "r"(a[0]), "r"(a[1]), "r"(a[2]), "r"(a[3]), "r"(b0), "r"(b1));
}

#define STR 72   // padded smem row stride in halves (144B -> conflict-free ldmatrix)

// ---------------- 1/sqrt(max(sum(mask),1)) ----------------
__global__ void reff_kernel(const float* __restrict__ mask) {
    int t = blockIdx.x * blockDim.x + threadIdx.x;
    if (t >= NTOK) return;
    const float4* m = (const float4*)(mask + (size_t)t * RR);
    float s = 0.f;
#pragma unroll
    for (int i = 0; i < RR / 4; i++) { float4 v = m[i]; s += v.x + v.y + v.z + v.w; }
    g_inv[t] = rsqrtf(fmaxf(s, 1.0f));
}

// ---------------- Q/K projection (fp32 compute, fp16 out) ----------------
__global__ __launch_bounds__(256) void proj_kernel(
    const float* __restrict__ x, const float* __restrict__ mask,
    const float* __restrict__ U, const float* __restrict__ Vw) {
    __shared__ float xs[16][64 + 1];
    __shared__ float ws[16][128];
    int m0 = blockIdx.x * 64;
    int tid = threadIdx.x;
    int ty = tid / 16, tx = tid % 16;
    float acc[4][8] = {};
    for (int k0 = 0; k0 < DD; k0 += 16) {
        {
            int i = tid >> 2, j = (tid & 3) * 4;
            float4 v = *(const float4*)(x + (size_t)(m0 + i) * DD + k0 + j);
            xs[j + 0][i] = v.x; xs[j + 1][i] = v.y; xs[j + 2][i] = v.z; xs[j + 3][i] = v.w;
        }
        {
            int j = tid >> 4, c0 = (tid & 15) * 8;
            const float* src = (c0 < 64) ? (U + (size_t)(k0 + j) * RR + c0)
                                         : (Vw + (size_t)(k0 + j) * RR + (c0 - 64));
            *(float4*)&ws[j][c0]     = *(const float4*)(src);
            *(float4*)&ws[j][c0 + 4] = *(const float4*)(src + 4);
        }
        __syncthreads();
#pragma unroll
        for (int k = 0; k < 16; k++) {
            float a[4], b[8];
#pragma unroll
            for (int i = 0; i < 4; i++) a[i] = xs[k][ty * 4 + i];
#pragma unroll
            for (int j = 0; j < 8; j++) b[j] = ws[k][tx * 8 + j];
#pragma unroll
            for (int i = 0; i < 4; i++)
#pragma unroll
                for (int j = 0; j < 8; j++) acc[i][j] += a[i] * b[j];
        }
        __syncthreads();
    }
#pragma unroll
    for (int i = 0; i < 4; i++) {
        int token = m0 + ty * 4 + i;
#pragma unroll
        for (int j = 0; j < 8; j++) {
            int c = tx * 8 + j;
            if (c < 64) {
                float mm = mask[(size_t)token * RR + c];
                g_Qh[(size_t)token * RR + c] = __float2half_rn(acc[i][j] * mm);
            } else {
                int r = c - 64;
                float mm = mask[(size_t)token * RR + r];
                g_Kh[(size_t)token * RR + r] = __float2half_rn(acc[i][j] * mm);
            }
        }
    }
}

// ---------------- x transpose: xt[b][d][n] = fp16(x[b][n][d]) ----------------
__global__ __launch_bounds__(256) void xt_kernel(const float* __restrict__ x) {
    __shared__ float t[32][33];
    int b = blockIdx.z, n0 = blockIdx.x * 32, d0 = blockIdx.y * 32;
    int tx = threadIdx.x & 31, ty = threadIdx.x >> 5;
    const float* xb = x + (size_t)b * NN * DD;
#pragma unroll
    for (int r = 0; r < 4; r++) {
        int i = ty + r * 8;
        t[i][tx] = xb[(size_t)(n0 + i) * DD + d0 + tx];
    }
    __syncthreads();
    __half* xt = g_xt + (size_t)b * DD * NN;
#pragma unroll
    for (int r = 0; r < 4; r++) {
        int j = ty + r * 8;
        xt[(size_t)(d0 + j) * NN + n0 + tx] = __float2half_rn(t[tx][j]);
    }
}

// ---------------- scores via HMMA: S[q][k] = (Qh[q,:].Kh[k,:]) * inv[q] ------
// block 128x128, K=64 one shot, 8 warps (4m x 2n), warp tile 32x64
__global__ __launch_bounds__(256) void scores_mma_kernel() {
    __shared__ __half As[128 * STR];
    __shared__ __half Bs[128 * STR];
    int b = blockIdx.z, q0 = blockIdx.y * 128, k0 = blockIdx.x * 128;
    int tid = threadIdx.x, wid = tid >> 5, lane = tid & 31;
    int wm = (wid & 3) * 32, wn = (wid >> 2) * 64;

    // load A (Qh) and B (Kh): 128 rows x 64 halves each
#pragma unroll
    for (int i = 0; i < 4; i++) {
        int idx = tid + i * 256;          // 0..1023
        int row = idx >> 3, col = (idx & 7) * 8;
        *(uint4*)&As[row * STR + col] =
            *(const uint4*)(g_Qh + (size_t)(b * NN + q0 + row) * RR + col);
        *(uint4*)&Bs[row * STR + col] =
            *(const uint4*)(g_Kh + (size_t)(b * NN + k0 + row) * RR + col);
    }
    __syncthreads();

    float acc[2][8][4] = {};
    uint32_t aBase = smem_u32(As), bBase = smem_u32(Bs);
#pragma unroll
    for (int kk = 0; kk < RR; kk += 16) {
        uint32_t a[2][4];
#pragma unroll
        for (int mf = 0; mf < 2; mf++) {
            int row = wm + mf * 16 + (lane & 15);
            ldsm_x4(a[mf][0], a[mf][1], a[mf][2], a[mf][3],
                    aBase + (uint32_t)(row * STR + kk + (lane >> 4) * 8) * 2);
        }
#pragma unroll
        for (int nf = 0; nf < 4; nf++) {
            int g = lane >> 3;
            int row = wn + nf * 16 + (lane & 7) + (g >> 1) * 8;
            uint32_t b0, b1, b2, b3;
            ldsm_x4(b0, b1, b2, b3,
                    bBase + (uint32_t)(row * STR + kk + (g & 1) * 8) * 2);
#pragma unroll
            for (int mf = 0; mf < 2; mf++) {
                mma16816(acc[mf][nf * 2],     a[mf], b0, b1);
                mma16816(acc[mf][nf * 2 + 1], a[mf], b2, b3);
            }
        }
    }

    float* Sb = g_S + (size_t)b * NN * NN;
#pragma unroll
    for (int mf = 0; mf < 2; mf++) {
        int r0 = q0 + wm + mf * 16 + lane / 4;
        float inv0 = g_inv[b * NN + r0];
        float inv1 = g_inv[b * NN + r0 + 8];
#pragma unroll
        for (int nf = 0; nf < 8; nf++) {
            int col = k0 + wn + nf * 8 + (lane & 3) * 2;
            *(float2*)&Sb[(size_t)r0 * NN + col] =
                make_float2(acc[mf][nf][0] * inv0, acc[mf][nf][1] * inv0);
            *(float2*)&Sb[(size_t)(r0 + 8) * NN + col] =
                make_float2(acc[mf][nf][2] * inv1, acc[mf][nf][3] * inv1);
        }
    }
}

// ---------------- softmax: read fp32 S, write fp16 P ----------------
__global__ __launch_bounds__(256) void softmax_kernel() {
    __shared__ float red[8];
    size_t row = blockIdx.x;
    const float* S = g_S + row * NN;
    __half* P = g_Ph + row * NN;
    int tid = threadIdx.x;
    float v[8];
    float4 a = *(const float4*)(S + tid * 8);
    float4 b = *(const float4*)(S + tid * 8 + 4);
    v[0] = a.x; v[1] = a.y; v[2] = a.z; v[3] = a.w;
    v[4] = b.x; v[5] = b.y; v[6] = b.z; v[7] = b.w;
    float m = -FLT_MAX;
#pragma unroll
    for (int i = 0; i < 8; i++) m = fmaxf(m, v[i]);
#pragma unroll
    for (int o = 16; o > 0; o >>= 1) m = fmaxf(m, __shfl_xor_sync(0xffffffffu, m, o));
    if ((tid & 31) == 0) red[tid >> 5] = m;
    __syncthreads();
    if (tid < 32) {
        float t = (tid < 8) ? red[tid] : -FLT_MAX;
#pragma unroll
        for (int o = 4; o > 0; o >>= 1) t = fmaxf(t, __shfl_xor_sync(0xffffffffu, t, o));
        if (tid == 0) red[0] = t;
    }
    __syncthreads();
    m = red[0];
    __syncthreads();
    float s = 0.f;
#pragma unroll
    for (int i = 0; i < 8; i++) { v[i] = __expf(v[i] - m); s += v[i]; }
#pragma unroll
    for (int o = 16; o > 0; o >>= 1) s += __shfl_xor_sync(0xffffffffu, s, o);
    if ((tid & 31) == 0) red[tid >> 5] = s;
    __syncthreads();
    if (tid < 32) {
        float t = (tid < 8) ? red[tid] : 0.f;
#pragma unroll
        for (int o = 4; o > 0; o >>= 1) t += __shfl_xor_sync(0xffffffffu, t, o);
        if (tid == 0) red[0] = t;
    }
    __syncthreads();
    float w = 1.0f / red[0];
    __half2 h0 = __floats2half2_rn(v[0] * w, v[1] * w);
    __half2 h1 = __floats2half2_rn(v[2] * w, v[3] * w);
    __half2 h2 = __floats2half2_rn(v[4] * w, v[5] * w);
    __half2 h3 = __floats2half2_rn(v[6] * w, v[7] * w);
    uint4 u;
    u.x = *(uint32_t*)&h0; u.y = *(uint32_t*)&h1;
    u.z = *(uint32_t*)&h2; u.w = *(uint32_t*)&h3;
    *(uint4*)(P + tid * 8) = u;
}

// ---------------- delta via HMMA: delta[q][d] = sum_t P[q][t] * xt[d][t] -----
// block 128x128, BK=64, 8 warps (4m x 2n), warp tile 32x64
__global__ __launch_bounds__(256) void delta_mma_kernel() {
    __shared__ __half As[128 * STR];
    __shared__ __half Bs[128 * STR];
    int b = blockIdx.z, q0 = blockIdx.y * 128, d0 = blockIdx.x * 128;
    const __half* Pb = g_Ph + (size_t)b * NN * NN;
    const __half* Xb = g_xt + (size_t)b * DD * NN;
    int tid = threadIdx.x, wid = tid >> 5, lane = tid & 31;
    int wm = (wid & 3) * 32, wn = (wid >> 2) * 64;
    uint32_t aBase = smem_u32(As), bBase = smem_u32(Bs);

    float acc[2][8][4] = {};
    for (int k0 = 0; k0 < NN; k0 += 64) {
#pragma unroll
        for (int i = 0; i < 4; i++) {
            int idx = tid + i * 256;
            int row = idx >> 3, col = (idx & 7) * 8;
            *(uint4*)&As[row * STR + col] =
                *(const uint4*)(Pb + (size_t)(q0 + row) * NN + k0 + col);
            *(uint4*)&Bs[row * STR + col] =
                *(const uint4*)(Xb + (size_t)(d0 + row) * NN + k0 + col);
        }
        __syncthreads();
#pragma unroll
        for (int kk = 0; kk < 64; kk += 16) {
            uint32_t a[2][4];
#pragma unroll
            for (int mf = 0; mf < 2; mf++) {
                int row = wm + mf * 16 + (lane & 15);
                ldsm_x4(a[mf][0], a[mf][1], a[mf][2], a[mf][3],
                        aBase + (uint32_t)(row * STR + kk + (lane >> 4) * 8) * 2);
            }
#pragma unroll
            for (int nf = 0; nf < 4; nf++) {
                int g = lane >> 3;
                int row = wn + nf * 16 + (lane & 7) + (g >> 1) * 8;
                uint32_t b0, b1, b2, b3;
                ldsm_x4(b0, b1, b2, b3,
                        bBase + (uint32_t)(row * STR + kk + (g & 1) * 8) * 2);
#pragma unroll
                for (int mf = 0; mf < 2; mf++) {
                    mma16816(acc[mf][nf * 2],     a[mf], b0, b1);
                    mma16816(acc[mf][nf * 2 + 1], a[mf], b2, b3);
                }
            }
        }
        __syncthreads();
    }

    float* dp = g_delta + ((size_t)b * NN + q0) * DD + d0;
#pragma unroll
    for (int mf = 0; mf < 2; mf++) {
        int row = wm + mf * 16 + lane / 4;
#pragma unroll
        for (int nf = 0; nf < 8; nf++) {
            int col = wn + nf * 8 + (lane & 3) * 2;
            *(float2*)&dp[(size_t)row * DD + col] =
                make_float2(acc[mf][nf][0], acc[mf][nf][1]);
            *(float2*)&dp[(size_t)(row + 8) * DD + col] =
                make_float2(acc[mf][nf][2], acc[mf][nf][3]);
        }
    }
}

// ---------------- out = LN(x + delta) ----------------
__global__ __launch_bounds__(256) void ln_kernel(
    const float* __restrict__ x, const float* __restrict__ gamma,
    const float* __restrict__ beta, float* __restrict__ out) {
    __shared__ float red[8];
    size_t token = blockIdx.x;
    const float* xr = x + token * DD;
    const float* dr = g_delta + token * DD;
    int tid = threadIdx.x;
    float4 xv = *(const float4*)(xr + tid * 4);
    float4 dv = *(const float4*)(dr + tid * 4);
    float y[4] = {xv.x + dv.x, xv.y + dv.y, xv.z + dv.z, xv.w + dv.w};
    float s = y[0] + y[1] + y[2] + y[3];
#pragma unroll
    for (int o = 16; o > 0; o >>= 1) s += __shfl_xor_sync(0xffffffffu, s, o);
    if ((tid & 31) == 0) red[tid >> 5] = s;
    __syncthreads();
    if (tid < 32) {
        float t = (tid < 8) ? red[tid] : 0.f;
#pragma unroll
        for (int o = 4; o > 0; o >>= 1) t += __shfl_xor_sync(0xffffffffu, t, o);
        if (tid == 0) red[0] = t;
    }
    __syncthreads();
    float mu = red[0] * (1.0f / DD);
    __syncthreads();
    float vs = 0.f;
#pragma unroll
    for (int i = 0; i < 4; i++) { float d = y[i] - mu; vs += d * d; }
#pragma unroll
    for (int o = 16; o > 0; o >>= 1) vs += __shfl_xor_sync(0xffffffffu, vs, o);
    if ((tid & 31) == 0) red[tid >> 5] = vs;
    __syncthreads();
    if (tid < 32) {
        float t = (tid < 8) ? red[tid] : 0.f;
#pragma unroll
        for (int o = 4; o > 0; o >>= 1) t += __shfl_xor_sync(0xffffffffu, t, o);
        if (tid == 0) red[0] = t;
    }
    __syncthreads();
    float inv = rsqrtf(red[0] * (1.0f / DD) + LN_EPS);
    float4 gv = *(const float4*)(gamma + tid * 4);
    float4 bv = *(const float4*)(beta + tid * 4);
    float4 o;
    o.x = (y[0] - mu) * inv * gv.x + bv.x;
    o.y = (y[1] - mu) * inv * gv.y + bv.y;
    o.z = (y[2] - mu) * inv * gv.z + bv.z;
    o.w = (y[3] - mu) * inv * gv.w + bv.w;
    *(float4*)(out + token * DD + tid * 4) = o;
}

extern "C" void kernel_launch(void* const* d_in, const int* in_sizes, int n_in,
                              void* d_out, int out_size) {
    const float* x     = (const float*)d_in[0];
    const float* mask  = (const float*)d_in[1];
    const float* U     = (const float*)d_in[2];
    const float* Vw    = (const float*)d_in[3];
    const float* gamma = (const float*)d_in[4];
    const float* beta  = (const float*)d_in[5];
    float* out = (float*)d_out;

    reff_kernel<<<(NTOK + 255) / 256, 256>>>(mask);
    proj_kernel<<<NTOK / 64, 256>>>(x, mask, U, Vw);
    xt_kernel<<<dim3(NN / 32, DD / 32, BB), 256>>>(x);
    scores_mma_kernel<<<dim3(NN / 128, NN / 128, BB), 256>>>();
    softmax_kernel<<<NTOK, 256>>>();
    delta_mma_kernel<<<dim3(DD / 128, NN / 128, BB), 256>>>();
    ln_kernel<<<NTOK, 256>>>(x, gamma, beta, out);
}

// round 5
// speedup vs baseline: 3.8402x; 1.0478x over previous
#include <cuda_runtime.h>
#include <cuda_fp16.h>
#include <math.h>
#include <float.h>
#include <stdint.h>

#define BB 4
#define NN 2048
#define DD 1024
#define RR 64
#define LN_EPS 1e-5f
#define NTOK (BB*NN)

// ---------------- scratch (no allocations allowed) ----------------
__device__ __half g_Qh[NTOK * RR];                    // 1 MB
__device__ __half g_Kh[NTOK * RR];                    // 1 MB
__device__ float  g_inv[NTOK];                        // 32 KB
__device__ __half g_Sh[(size_t)BB * NN * NN];         // 32 MB scores (fp16)
__device__ __half g_Ph[(size_t)BB * NN * NN];         // 32 MB probs  (fp16)
__device__ __half g_xt[(size_t)BB * DD * NN];         // 16 MB x^T    (fp16)
__device__ float  g_delta[(size_t)BB * NN * DD];      // 32 MB

// ================= warp-mma helpers (sm_80+ path, legal on compute_103) =====
__device__ __forceinline__ uint32_t smem_u32(const void* p) {
    uint32_t a;
    asm("{ .reg .u64 t; cvta.to.shared.u64 t, %1; cvt.u32.u64 %0, t; }" : "=r"(a) : "l"(p));
    return a;
}
__device__ __forceinline__ void ldsm_x4(uint32_t& r0, uint32_t& r1, uint32_t& r2,
                                        uint32_t& r3, uint32_t addr) {
    asm volatile("ldmatrix.sync.aligned.m8n8.x4.shared.b16 {%0,%1,%2,%3}, [%4];"
                 : "=r"(r0), "=r"(r1), "=r"(r2), "=r"(r3) : "r"(addr));
}
__device__ __forceinline__ void mma16816(float* c, const uint32_t* a,
                                         uint32_t b0, uint32_t b1) {
    asm volatile("mma.sync.aligned.m16n8k16.row.col.f32.f16.f16.f32 "
                 "{%0,%1,%2,%3}, {%4,%5,%6,%7}, {%8,%9}, {%0,%1,%2,%3};"
                 : "+f"(c[0]), "+f"(c[1]), "+f"(c[2]), "+f"(c[3])
                 : "r"(a[0]), "r"(a[1]), "r"(a[2]), "r"(a[3]), "r"(b0), "r"(b1));
}
__device__ __forceinline__ void cp_async16(uint32_t saddr, const void* gp) {
    size_t ga = __cvta_generic_to_global(gp);
    asm volatile("cp.async.cg.shared.global [%0], [%1], 16;" :: "r"(saddr), "l"(ga) : "memory");
}
__device__ __forceinline__ void cp_commit() {
    asm volatile("cp.async.commit_group;" ::: "memory");
}
template <int N> __device__ __forceinline__ void cp_wait() {
    asm volatile("cp.async.wait_group %0;" :: "n"(N) : "memory");
}

#define STR 72   // padded smem row stride in halves (144B -> conflict-free ldmatrix)

// ---------------- 1/sqrt(max(sum(mask),1)) ----------------
__global__ void reff_kernel(const float* __restrict__ mask) {
    int t = blockIdx.x * blockDim.x + threadIdx.x;
    if (t >= NTOK) return;
    const float4* m = (const float4*)(mask + (size_t)t * RR);
    float s = 0.f;
#pragma unroll
    for (int i = 0; i < RR / 4; i++) { float4 v = m[i]; s += v.x + v.y + v.z + v.w; }
    g_inv[t] = rsqrtf(fmaxf(s, 1.0f));
}

// ---------------- Q/K projection (fp32 compute, fp16 out) ----------------
__global__ __launch_bounds__(256) void proj_kernel(
    const float* __restrict__ x, const float* __restrict__ mask,
    const float* __restrict__ U, const float* __restrict__ Vw) {
    __shared__ float xs[16][64 + 1];
    __shared__ float ws[16][128];
    int m0 = blockIdx.x * 64;
    int tid = threadIdx.x;
    int ty = tid / 16, tx = tid % 16;
    float acc[4][8] = {};
    for (int k0 = 0; k0 < DD; k0 += 16) {
        {
            int i = tid >> 2, j = (tid & 3) * 4;
            float4 v = *(const float4*)(x + (size_t)(m0 + i) * DD + k0 + j);
            xs[j + 0][i] = v.x; xs[j + 1][i] = v.y; xs[j + 2][i] = v.z; xs[j + 3][i] = v.w;
        }
        {
            int j = tid >> 4, c0 = (tid & 15) * 8;
            const float* src = (c0 < 64) ? (U + (size_t)(k0 + j) * RR + c0)
                                         : (Vw + (size_t)(k0 + j) * RR + (c0 - 64));
            *(float4*)&ws[j][c0]     = *(const float4*)(src);
            *(float4*)&ws[j][c0 + 4] = *(const float4*)(src + 4);
        }
        __syncthreads();
#pragma unroll
        for (int k = 0; k < 16; k++) {
            float a[4], b[8];
#pragma unroll
            for (int i = 0; i < 4; i++) a[i] = xs[k][ty * 4 + i];
#pragma unroll
            for (int j = 0; j < 8; j++) b[j] = ws[k][tx * 8 + j];
#pragma unroll
            for (int i = 0; i < 4; i++)
#pragma unroll
                for (int j = 0; j < 8; j++) acc[i][j] += a[i] * b[j];
        }
        __syncthreads();
    }
#pragma unroll
    for (int i = 0; i < 4; i++) {
        int token = m0 + ty * 4 + i;
#pragma unroll
        for (int j = 0; j < 8; j++) {
            int c = tx * 8 + j;
            if (c < 64) {
                float mm = mask[(size_t)token * RR + c];
                g_Qh[(size_t)token * RR + c] = __float2half_rn(acc[i][j] * mm);
            } else {
                int r = c - 64;
                float mm = mask[(size_t)token * RR + r];
                g_Kh[(size_t)token * RR + r] = __float2half_rn(acc[i][j] * mm);
            }
        }
    }
}

// ---------------- x transpose: xt[b][d][n] = fp16(x[b][n][d]) ----------------
__global__ __launch_bounds__(256) void xt_kernel(const float* __restrict__ x) {
    __shared__ float t[32][33];
    int b = blockIdx.z, n0 = blockIdx.x * 32, d0 = blockIdx.y * 32;
    int tx = threadIdx.x & 31, ty = threadIdx.x >> 5;
    const float* xb = x + (size_t)b * NN * DD;
#pragma unroll
    for (int r = 0; r < 4; r++) {
        int i = ty + r * 8;
        t[i][tx] = xb[(size_t)(n0 + i) * DD + d0 + tx];
    }
    __syncthreads();
    __half* xt = g_xt + (size_t)b * DD * NN;
#pragma unroll
    for (int r = 0; r < 4; r++) {
        int j = ty + r * 8;
        xt[(size_t)(d0 + j) * NN + n0 + tx] = __float2half_rn(t[tx][j]);
    }
}

// ---------------- scores via HMMA: Sh[q][k] = fp16((Qh.Kh)*inv[q]) ----------
__global__ __launch_bounds__(256) void scores_mma_kernel() {
    __shared__ __half As[128 * STR];
    __shared__ __half Bs[128 * STR];
    int b = blockIdx.z, q0 = blockIdx.y * 128, k0 = blockIdx.x * 128;
    int tid = threadIdx.x, wid = tid >> 5, lane = tid & 31;
    int wm = (wid & 3) * 32, wn = (wid >> 2) * 64;

#pragma unroll
    for (int i = 0; i < 4; i++) {
        int idx = tid + i * 256;
        int row = idx >> 3, col = (idx & 7) * 8;
        *(uint4*)&As[row * STR + col] =
            *(const uint4*)(g_Qh + (size_t)(b * NN + q0 + row) * RR + col);
        *(uint4*)&Bs[row * STR + col] =
            *(const uint4*)(g_Kh + (size_t)(b * NN + k0 + row) * RR + col);
    }
    __syncthreads();

    float acc[2][8][4] = {};
    uint32_t aBase = smem_u32(As), bBase = smem_u32(Bs);
#pragma unroll
    for (int kk = 0; kk < RR; kk += 16) {
        uint32_t a[2][4];
#pragma unroll
        for (int mf = 0; mf < 2; mf++) {
            int row = wm + mf * 16 + (lane & 15);
            ldsm_x4(a[mf][0], a[mf][1], a[mf][2], a[mf][3],
                    aBase + (uint32_t)(row * STR + kk + (lane >> 4) * 8) * 2);
        }
#pragma unroll
        for (int nf = 0; nf < 4; nf++) {
            int g = lane >> 3;
            int row = wn + nf * 16 + (lane & 7) + (g >> 1) * 8;
            uint32_t b0, b1, b2, b3;
            ldsm_x4(b0, b1, b2, b3,
                    bBase + (uint32_t)(row * STR + kk + (g & 1) * 8) * 2);
#pragma unroll
            for (int mf = 0; mf < 2; mf++) {
                mma16816(acc[mf][nf * 2],     a[mf], b0, b1);
                mma16816(acc[mf][nf * 2 + 1], a[mf], b2, b3);
            }
        }
    }

    __half* Sb = g_Sh + (size_t)b * NN * NN;
#pragma unroll
    for (int mf = 0; mf < 2; mf++) {
        int r0 = q0 + wm + mf * 16 + lane / 4;
        float inv0 = g_inv[b * NN + r0];
        float inv1 = g_inv[b * NN + r0 + 8];
#pragma unroll
        for (int nf = 0; nf < 8; nf++) {
            int col = k0 + wn + nf * 8 + (lane & 3) * 2;
            *(__half2*)&Sb[(size_t)r0 * NN + col] =
                __floats2half2_rn(acc[mf][nf][0] * inv0, acc[mf][nf][1] * inv0);
            *(__half2*)&Sb[(size_t)(r0 + 8) * NN + col] =
                __floats2half2_rn(acc[mf][nf][2] * inv1, acc[mf][nf][3] * inv1);
        }
    }
}

// ---------------- softmax: read fp16 S, write fp16 P ----------------
__global__ __launch_bounds__(256) void softmax_kernel() {
    __shared__ float red[8];
    size_t row = blockIdx.x;
    const __half* S = g_Sh + row * NN;
    __half* P = g_Ph + row * NN;
    int tid = threadIdx.x;
    uint4 u = *(const uint4*)(S + tid * 8);
    __half2* hs = reinterpret_cast<__half2*>(&u);
    float v[8];
#pragma unroll
    for (int i = 0; i < 4; i++) {
        float2 f = __half22float2(hs[i]);
        v[i * 2] = f.x; v[i * 2 + 1] = f.y;
    }
    float m = -FLT_MAX;
#pragma unroll
    for (int i = 0; i < 8; i++) m = fmaxf(m, v[i]);
#pragma unroll
    for (int o = 16; o > 0; o >>= 1) m = fmaxf(m, __shfl_xor_sync(0xffffffffu, m, o));
    if ((tid & 31) == 0) red[tid >> 5] = m;
    __syncthreads();
    if (tid < 32) {
        float t = (tid < 8) ? red[tid] : -FLT_MAX;
#pragma unroll
        for (int o = 4; o > 0; o >>= 1) t = fmaxf(t, __shfl_xor_sync(0xffffffffu, t, o));
        if (tid == 0) red[0] = t;
    }
    __syncthreads();
    m = red[0];
    __syncthreads();
    float s = 0.f;
#pragma unroll
    for (int i = 0; i < 8; i++) { v[i] = __expf(v[i] - m); s += v[i]; }
#pragma unroll
    for (int o = 16; o > 0; o >>= 1) s += __shfl_xor_sync(0xffffffffu, s, o);
    if ((tid & 31) == 0) red[tid >> 5] = s;
    __syncthreads();
    if (tid < 32) {
        float t = (tid < 8) ? red[tid] : 0.f;
#pragma unroll
        for (int o = 4; o > 0; o >>= 1) t += __shfl_xor_sync(0xffffffffu, t, o);
        if (tid == 0) red[0] = t;
    }
    __syncthreads();
    float w = 1.0f / red[0];
    __half2 h0 = __floats2half2_rn(v[0] * w, v[1] * w);
    __half2 h1 = __floats2half2_rn(v[2] * w, v[3] * w);
    __half2 h2 = __floats2half2_rn(v[4] * w, v[5] * w);
    __half2 h3 = __floats2half2_rn(v[6] * w, v[7] * w);
    uint4 o;
    o.x = *(uint32_t*)&h0; o.y = *(uint32_t*)&h1;
    o.z = *(uint32_t*)&h2; o.w = *(uint32_t*)&h3;
    *(uint4*)(P + tid * 8) = o;
}

// ---------------- delta via HMMA + 3-stage cp.async pipeline ----------------
// block 128x128, BK=64, 8 warps (4m x 2n), warp tile 32x64
#define DSTAGE (128 * STR)   // halves per operand per stage
#define DSMEM_BYTES (3 * 2 * DSTAGE * 2)

__device__ __forceinline__ void delta_load_stage(
    uint32_t sBase, const __half* Pb, const __half* Xb,
    int q0, int d0, int tid, int s, int k0) {
#pragma unroll
    for (int i = 0; i < 4; i++) {
        int u = tid + i * 256;
        int row = u >> 3, col = (u & 7) * 8;
        cp_async16(sBase + (uint32_t)((s * 2) * DSTAGE + row * STR + col) * 2,
                   Pb + (size_t)(q0 + row) * NN + k0 + col);
        cp_async16(sBase + (uint32_t)((s * 2 + 1) * DSTAGE + row * STR + col) * 2,
                   Xb + (size_t)(d0 + row) * NN + k0 + col);
    }
    cp_commit();
}

__global__ __launch_bounds__(256) void delta_mma_kernel() {
    extern __shared__ __half dsm[];
    int b = blockIdx.z, q0 = blockIdx.y * 128, d0 = blockIdx.x * 128;
    const __half* Pb = g_Ph + (size_t)b * NN * NN;
    const __half* Xb = g_xt + (size_t)b * DD * NN;
    int tid = threadIdx.x, wid = tid >> 5, lane = tid & 31;
    int wm = (wid & 3) * 32, wn = (wid >> 2) * 64;
    uint32_t sBase = smem_u32(dsm);

    delta_load_stage(sBase, Pb, Xb, q0, d0, tid, 0, 0);
    delta_load_stage(sBase, Pb, Xb, q0, d0, tid, 1, 64);

    float acc[2][8][4] = {};
    for (int c = 0; c < NN / 64; c++) {
        int s = c % 3;
        if (c < NN / 64 - 1) cp_wait<1>(); else cp_wait<0>();
        __syncthreads();
        if (c + 2 < NN / 64)
            delta_load_stage(sBase, Pb, Xb, q0, d0, tid, (c + 2) % 3, (c + 2) * 64);
        uint32_t aBase = sBase + (uint32_t)(s * 2) * DSTAGE * 2;
        uint32_t bBase = sBase + (uint32_t)(s * 2 + 1) * DSTAGE * 2;
#pragma unroll
        for (int kk = 0; kk < 64; kk += 16) {
            uint32_t a[2][4];
#pragma unroll
            for (int mf = 0; mf < 2; mf++) {
                int row = wm + mf * 16 + (lane & 15);
                ldsm_x4(a[mf][0], a[mf][1], a[mf][2], a[mf][3],
                        aBase + (uint32_t)(row * STR + kk + (lane >> 4) * 8) * 2);
            }
#pragma unroll
            for (int nf = 0; nf < 4; nf++) {
                int g = lane >> 3;
                int row = wn + nf * 16 + (lane & 7) + (g >> 1) * 8;
                uint32_t b0, b1, b2, b3;
                ldsm_x4(b0, b1, b2, b3,
                        bBase + (uint32_t)(row * STR + kk + (g & 1) * 8) * 2);
#pragma unroll
                for (int mf = 0; mf < 2; mf++) {
                    mma16816(acc[mf][nf * 2],     a[mf], b0, b1);
                    mma16816(acc[mf][nf * 2 + 1], a[mf], b2, b3);
                }
            }
        }
    }

    float* dp = g_delta + ((size_t)b * NN + q0) * DD + d0;
#pragma unroll
    for (int mf = 0; mf < 2; mf++) {
        int row = wm + mf * 16 + lane / 4;
#pragma unroll
        for (int nf = 0; nf < 8; nf++) {
            int col = wn + nf * 8 + (lane & 3) * 2;
            *(float2*)&dp[(size_t)row * DD + col] =
                make_float2(acc[mf][nf][0], acc[mf][nf][1]);
            *(float2*)&dp[(size_t)(row + 8) * DD + col] =
                make_float2(acc[mf][nf][2], acc[mf][nf][3]);
        }
    }
}

// ---------------- out = LN(x + delta) ----------------
__global__ __launch_bounds__(256) void ln_kernel(
    const float* __restrict__ x, const float* __restrict__ gamma,
    const float* __restrict__ beta, float* __restrict__ out) {
    __shared__ float red[8];
    size_t token = blockIdx.x;
    const float* xr = x + token * DD;
    const float* dr = g_delta + token * DD;
    int tid = threadIdx.x;
    float4 xv = *(const float4*)(xr + tid * 4);
    float4 dv = *(const float4*)(dr + tid * 4);
    float y[4] = {xv.x + dv.x, xv.y + dv.y, xv.z + dv.z, xv.w + dv.w};
    float s = y[0] + y[1] + y[2] + y[3];
#pragma unroll
    for (int o = 16; o > 0; o >>= 1) s += __shfl_xor_sync(0xffffffffu, s, o);
    if ((tid & 31) == 0) red[tid >> 5] = s;
    __syncthreads();
    if (tid < 32) {
        float t = (tid < 8) ? red[tid] : 0.f;
#pragma unroll
        for (int o = 4; o > 0; o >>= 1) t += __shfl_xor_sync(0xffffffffu, t, o);
        if (tid == 0) red[0] = t;
    }
    __syncthreads();
    float mu = red[0] * (1.0f / DD);
    __syncthreads();
    float vs = 0.f;
#pragma unroll
    for (int i = 0; i < 4; i++) { float d = y[i] - mu; vs += d * d; }
#pragma unroll
    for (int o = 16; o > 0; o >>= 1) vs += __shfl_xor_sync(0xffffffffu, vs, o);
    if ((tid & 31) == 0) red[tid >> 5] = vs;
    __syncthreads();
    if (tid < 32) {
        float t = (tid < 8) ? red[tid] : 0.f;
#pragma unroll
        for (int o = 4; o > 0; o >>= 1) t += __shfl_xor_sync(0xffffffffu, t, o);
        if (tid == 0) red[0] = t;
    }
    __syncthreads();
    float inv = rsqrtf(red[0] * (1.0f / DD) + LN_EPS);
    float4 gv = *(const float4*)(gamma + tid * 4);
    float4 bv = *(const float4*)(beta + tid * 4);
    float4 o;
    o.x = (y[0] - mu) * inv * gv.x + bv.x;
    o.y = (y[1] - mu) * inv * gv.y + bv.y;
    o.z = (y[2] - mu) * inv * gv.z + bv.z;
    o.w = (y[3] - mu) * inv * gv.w + bv.w;
    *(float4*)(out + token * DD + tid * 4) = o;
}

extern "C" void kernel_launch(void* const* d_in, const int* in_sizes, int n_in,
                              void* d_out, int out_size) {
    const float* x     = (const float*)d_in[0];
    const float* mask  = (const float*)d_in[1];
    const float* U     = (const float*)d_in[2];
    const float* Vw    = (const float*)d_in[3];
    const float* gamma = (const float*)d_in[4];
    const float* beta  = (const float*)d_in[5];
    float* out = (float*)d_out;

    static bool attr_done = false;
    if (!attr_done) {
        cudaFuncSetAttribute(delta_mma_kernel,
                             cudaFuncAttributeMaxDynamicSharedMemorySize, DSMEM_BYTES);
        attr_done = true;
    }

    reff_kernel<<<(NTOK + 255) / 256, 256>>>(mask);
    proj_kernel<<<NTOK / 64, 256>>>(x, mask, U, Vw);
    xt_kernel<<<dim3(NN / 32, DD / 32, BB), 256>>>(x);
    scores_mma_kernel<<<dim3(NN / 128, NN / 128, BB), 256>>>();
    softmax_kernel<<<NTOK, 256>>>();
    delta_mma_kernel<<<dim3(DD / 128, NN / 128, BB), 256, DSMEM_BYTES>>>();
    ln_kernel<<<NTOK, 256>>>(x, gamma, beta, out);
}

// round 7
// speedup vs baseline: 6.2234x; 1.6206x over previous
#include <cuda_runtime.h>
#include <cuda_fp16.h>
#include <math.h>
#include <float.h>
#include <stdint.h>

#define BB 4
#define NN 2048
#define DD 1024
#define RR 64
#define LN_EPS 1e-5f
#define NTOK (BB*NN)
#define ESHIFT 10.0f

// ---------------- scratch (no allocations allowed) ----------------
__device__ __half g_Qh[NTOK * RR];                    // 1 MB
__device__ __half g_Kh[NTOK * RR];                    // 1 MB
__device__ float  g_inv[NTOK];                        // 32 KB
__device__ float  g_L[NTOK];                          // 32 KB row sums of E
__device__ __half g_Ph[(size_t)BB * NN * NN];         // 32 MB E=exp(s-SHIFT) fp16
__device__ __half g_xt[(size_t)BB * DD * NN];         // 16 MB x^T fp16
__device__ __half g_xh[(size_t)BB * NN * DD];         // 16 MB x   fp16
__device__ __half g_Ut[RR * DD];                      // 128 KB U^T fp16
__device__ __half g_Vt[RR * DD];                      // 128 KB V^T fp16
__device__ float  g_delta[(size_t)BB * NN * DD];      // 32 MB

// ================= warp-mma helpers (sm_80+ path, legal on compute_103) =====
__device__ __forceinline__ uint32_t smem_u32(const void* p) {
    uint32_t a;
    asm("{ .reg .u64 t; cvta.to.shared.u64 t, %1; cvt.u32.u64 %0, t; }" : "=r"(a) : "l"(p));
    return a;
}
__device__ __forceinline__ void ldsm_x4(uint32_t& r0, uint32_t& r1, uint32_t& r2,
                                        uint32_t& r3, uint32_t addr) {
    asm volatile("ldmatrix.sync.aligned.m8n8.x4.shared.b16 {%0,%1,%2,%3}, [%4];"
                 : "=r"(r0), "=r"(r1), "=r"(r2), "=r"(r3) : "r"(addr));
}
__device__ __forceinline__ void mma16816(float* c, const uint32_t* a,
                                         uint32_t b0, uint32_t b1) {
    asm volatile("mma.sync.aligned.m16n8k16.row.col.f32.f16.f16.f32 "
                 "{%0,%1,%2,%3}, {%4,%5,%6,%7}, {%8,%9}, {%0,%1,%2,%3};"
                 : "+f"(c[0]), "+f"(c[1]), "+f"(c[2]), "+f"(c[3])
                 : "r"(a[0]), "r"(a[1]), "r"(a[2]), "r"(a[3]), "r"(b0), "r"(b1));
}
__device__ __forceinline__ void cp_async16(uint32_t saddr, const void* gp) {
    size_t ga = __cvta_generic_to_global(gp);
    asm volatile("cp.async.cg.shared.global [%0], [%1], 16;" :: "r"(saddr), "l"(ga) : "memory");
}
__device__ __forceinline__ void cp_commit() {
    asm volatile("cp.async.commit_group;" ::: "memory");
}
template <int N> __device__ __forceinline__ void cp_wait() {
    asm volatile("cp.async.wait_group %0;" :: "n"(N) : "memory");
}

#define STR 72   // padded smem row stride in halves (144B -> conflict-free ldmatrix)

// ---------------- per token: inv=1/sqrt(max(sum mask,1)); zero L -------------
__global__ void reff_kernel(const float* __restrict__ mask) {
    int t = blockIdx.x * blockDim.x + threadIdx.x;
    if (t >= NTOK) return;
    const float4* m = (const float4*)(mask + (size_t)t * RR);
    float s = 0.f;
#pragma unroll
    for (int i = 0; i < RR / 4; i++) { float4 v = m[i]; s += v.x + v.y + v.z + v.w; }
    g_inv[t] = rsqrtf(fmaxf(s, 1.0f));
    g_L[t] = 0.f;
}

// ---------------- x -> xh (fp16 row-major) and xt (fp16 d-major) -------------
__global__ __launch_bounds__(256) void xt_kernel(const float* __restrict__ x) {
    __shared__ float t[32][33];
    int b = blockIdx.z, n0 = blockIdx.x * 32, d0 = blockIdx.y * 32;
    int tx = threadIdx.x & 31, ty = threadIdx.x >> 5;
    const float* xb = x + (size_t)b * NN * DD;
#pragma unroll
    for (int r = 0; r < 4; r++) {
        int i = ty + r * 8;
        float v = xb[(size_t)(n0 + i) * DD + d0 + tx];
        t[i][tx] = v;
        g_xh[(size_t)(b * NN + n0 + i) * DD + d0 + tx] = __float2half_rn(v);
    }
    __syncthreads();
    __half* xt = g_xt + (size_t)b * DD * NN;
#pragma unroll
    for (int r = 0; r < 4; r++) {
        int j = ty + r * 8;
        xt[(size_t)(d0 + j) * NN + n0 + tx] = __float2half_rn(t[tx][j]);
    }
}

// ---------------- U,V -> Ut,Vt (fp16, [R][D]) --------------------------------
__global__ __launch_bounds__(256) void wt_kernel(const float* __restrict__ U,
                                                 const float* __restrict__ V) {
    __shared__ float t[32][33];
    int d0 = blockIdx.x * 32, r0 = blockIdx.y * 32;
    const float* W = blockIdx.z ? V : U;
    __half* O = blockIdx.z ? g_Vt : g_Ut;
    int tx = threadIdx.x & 31, ty = threadIdx.x >> 5;
#pragma unroll
    for (int r = 0; r < 4; r++) {
        int i = ty + r * 8;                 // d index
        t[i][tx] = W[(size_t)(d0 + i) * RR + r0 + tx];
    }
    __syncthreads();
#pragma unroll
    for (int r = 0; r < 4; r++) {
        int j = ty + r * 8;                 // r index
        O[(size_t)(r0 + j) * DD + d0 + tx] = __float2half_rn(t[tx][j]);
    }
}

// ---------------- proj via HMMA: Q/K = (xh @ [Ut|Vt]^T) * mask ---------------
// block: 64 tokens x 128 cols (Q 0..63 | K 64..127), BK=64, 8 warps (2m x 4n)
#define PSTAGE_A (64 * STR)
#define PSTAGE_B (128 * STR)
#define PSTAGE   (PSTAGE_A + PSTAGE_B)
#define PSMEM_BYTES (3 * PSTAGE * 2)

__device__ __forceinline__ void proj_load_stage(uint32_t sBase, const __half* Xrow,
                                                int tid, int s, int k0) {
    uint32_t aOff = sBase + (uint32_t)(s * PSTAGE) * 2;
    uint32_t bOff = sBase + (uint32_t)(s * PSTAGE + PSTAGE_A) * 2;
#pragma unroll
    for (int i = 0; i < 2; i++) {
        int u = tid + i * 256;              // 0..511
        int row = u >> 3, col = (u & 7) * 8;
        cp_async16(aOff + (uint32_t)(row * STR + col) * 2,
                   Xrow + (size_t)row * DD + k0 + col);
    }
#pragma unroll
    for (int i = 0; i < 4; i++) {
        int u = tid + i * 256;              // 0..1023
        int row = u >> 3, col = (u & 7) * 8;
        const __half* src = (row < 64) ? (g_Ut + (size_t)row * DD + k0 + col)
                                       : (g_Vt + (size_t)(row - 64) * DD + k0 + col);
        cp_async16(bOff + (uint32_t)(row * STR + col) * 2, src);
    }
    cp_commit();
}

__global__ __launch_bounds__(256, 2) void proj_mma_kernel(const float* __restrict__ mask) {
    extern __shared__ __half psm[];
    int t0 = blockIdx.x * 64;
    int tid = threadIdx.x, wid = tid >> 5, lane = tid & 31;
    int wm = (wid & 1) * 32, wn = (wid >> 1) * 32;
    uint32_t sBase = smem_u32(psm);
    const __half* Xrow = g_xh + (size_t)t0 * DD;

    proj_load_stage(sBase, Xrow, tid, 0, 0);
    proj_load_stage(sBase, Xrow, tid, 1, 64);

    float acc[2][4][4] = {};
    for (int c = 0; c < DD / 64; c++) {
        int s = c % 3;
        if (c < DD / 64 - 1) cp_wait<1>(); else cp_wait<0>();
        __syncthreads();
        if (c + 2 < DD / 64) proj_load_stage(sBase, Xrow, tid, (c + 2) % 3, (c + 2) * 64);
        uint32_t aBase = sBase + (uint32_t)(s * PSTAGE) * 2;
        uint32_t bBase = sBase + (uint32_t)(s * PSTAGE + PSTAGE_A) * 2;
#pragma unroll
        for (int kk = 0; kk < 64; kk += 16) {
            uint32_t a[2][4];
#pragma unroll
            for (int mf = 0; mf < 2; mf++) {
                int row = wm + mf * 16 + (lane & 15);
                ldsm_x4(a[mf][0], a[mf][1], a[mf][2], a[mf][3],
                        aBase + (uint32_t)(row * STR + kk + (lane >> 4) * 8) * 2);
            }
#pragma unroll
            for (int nf = 0; nf < 2; nf++) {
                int g = lane >> 3;
                int row = wn + nf * 16 + (lane & 7) + (g >> 1) * 8;
                uint32_t b0, b1, b2, b3;
                ldsm_x4(b0, b1, b2, b3,
                        bBase + (uint32_t)(row * STR + kk + (g & 1) * 8) * 2);
#pragma unroll
                for (int mf = 0; mf < 2; mf++) {
                    mma16816(acc[mf][nf * 2],     a[mf], b0, b1);
                    mma16816(acc[mf][nf * 2 + 1], a[mf], b2, b3);
                }
            }
        }
        __syncthreads();
    }

#pragma unroll
    for (int mf = 0; mf < 2; mf++) {
#pragma unroll
        for (int rr = 0; rr < 2; rr++) {
            int token = t0 + wm + mf * 16 + lane / 4 + rr * 8;
#pragma unroll
            for (int nn = 0; nn < 4; nn++) {
                int col = wn + nn * 8 + (lane & 3) * 2;
                float v0 = acc[mf][nn][rr * 2], v1 = acc[mf][nn][rr * 2 + 1];
                int r = (col < 64) ? col : col - 64;
                float2 mm = *(const float2*)(mask + (size_t)token * RR + r);
                __half2 h = __floats2half2_rn(v0 * mm.x, v1 * mm.y);
                __half* dst = (col < 64) ? g_Qh : g_Kh;
                *(__half2*)&dst[(size_t)token * RR + r] = h;
            }
        }
    }
}

// ---- scores+exp: E[q][k] = fp16(exp(QK*inv[q] - SHIFT)); L[q] += rowsum -----
__global__ __launch_bounds__(256, 2) void scores_mma_kernel() {
    __shared__ __half As[128 * STR];
    __shared__ __half Bs[128 * STR];
    int b = blockIdx.z, q0 = blockIdx.y * 128, k0 = blockIdx.x * 128;
    int tid = threadIdx.x, wid = tid >> 5, lane = tid & 31;
    int wm = (wid & 3) * 32, wn = (wid >> 2) * 64;

#pragma unroll
    for (int i = 0; i < 4; i++) {
        int idx = tid + i * 256;
        int row = idx >> 3, col = (idx & 7) * 8;
        *(uint4*)&As[row * STR + col] =
            *(const uint4*)(g_Qh + (size_t)(b * NN + q0 + row) * RR + col);
        *(uint4*)&Bs[row * STR + col] =
            *(const uint4*)(g_Kh + (size_t)(b * NN + k0 + row) * RR + col);
    }
    __syncthreads();

    float acc[2][8][4] = {};
    uint32_t aBase = smem_u32(As), bBase = smem_u32(Bs);
#pragma unroll
    for (int kk = 0; kk < RR; kk += 16) {
        uint32_t a[2][4];
#pragma unroll
        for (int mf = 0; mf < 2; mf++) {
            int row = wm + mf * 16 + (lane & 15);
            ldsm_x4(a[mf][0], a[mf][1], a[mf][2], a[mf][3],
                    aBase + (uint32_t)(row * STR + kk + (lane >> 4) * 8) * 2);
        }
#pragma unroll
        for (int nf = 0; nf < 4; nf++) {
            int g = lane >> 3;
            int row = wn + nf * 16 + (lane & 7) + (g >> 1) * 8;
            uint32_t b0, b1, b2, b3;
            ldsm_x4(b0, b1, b2, b3,
                    bBase + (uint32_t)(row * STR + kk + (g & 1) * 8) * 2);
#pragma unroll
            for (int mf = 0; mf < 2; mf++) {
                mma16816(acc[mf][nf * 2],     a[mf], b0, b1);
                mma16816(acc[mf][nf * 2 + 1], a[mf], b2, b3);
            }
        }
    }

    __half* Pb = g_Ph + (size_t)b * NN * NN;
#pragma unroll
    for (int mf = 0; mf < 2; mf++) {
        int r0 = q0 + wm + mf * 16 + lane / 4;
        float inv0 = g_inv[b * NN + r0];
        float inv1 = g_inv[b * NN + r0 + 8];
        float sum0 = 0.f, sum1 = 0.f;
#pragma unroll
        for (int nf = 0; nf < 8; nf++) {
            int col = k0 + wn + nf * 8 + (lane & 3) * 2;
            __half2 h0 = __floats2half2_rn(__expf(acc[mf][nf][0] * inv0 - ESHIFT),
                                           __expf(acc[mf][nf][1] * inv0 - ESHIFT));
            __half2 h1 = __floats2half2_rn(__expf(acc[mf][nf][2] * inv1 - ESHIFT),
                                           __expf(acc[mf][nf][3] * inv1 - ESHIFT));
            *(__half2*)&Pb[(size_t)r0 * NN + col] = h0;
            *(__half2*)&Pb[(size_t)(r0 + 8) * NN + col] = h1;
            float2 f0 = __half22float2(h0), f1 = __half22float2(h1);
            sum0 += f0.x + f0.y;
            sum1 += f1.x + f1.y;
        }
        sum0 += __shfl_xor_sync(0xffffffffu, sum0, 1);
        sum0 += __shfl_xor_sync(0xffffffffu, sum0, 2);
        sum1 += __shfl_xor_sync(0xffffffffu, sum1, 1);
        sum1 += __shfl_xor_sync(0xffffffffu, sum1, 2);
        if ((lane & 3) == 0) {
            atomicAdd(&g_L[b * NN + r0], sum0);
            atomicAdd(&g_L[b * NN + r0 + 8], sum1);
        }
    }
}

// ---------------- delta = (E @ x) / L : HMMA + 3-stage cp.async --------------
#define DSTAGE (128 * STR)
#define DSMEM_BYTES (3 * 2 * DSTAGE * 2)

__device__ __forceinline__ void delta_load_stage(
    uint32_t sBase, const __half* Pb, const __half* Xb,
    int q0, int d0, int tid, int s, int k0) {
#pragma unroll
    for (int i = 0; i < 4; i++) {
        int u = tid + i * 256;
        int row = u >> 3, col = (u & 7) * 8;
        cp_async16(sBase + (uint32_t)((s * 2) * DSTAGE + row * STR + col) * 2,
                   Pb + (size_t)(q0 + row) * NN + k0 + col);
        cp_async16(sBase + (uint32_t)((s * 2 + 1) * DSTAGE + row * STR + col) * 2,
                   Xb + (size_t)(d0 + row) * NN + k0 + col);
    }
    cp_commit();
}

__global__ __launch_bounds__(256, 2) void delta_mma_kernel() {
    extern __shared__ __half dsm[];
    int b = blockIdx.z, q0 = blockIdx.y * 128, d0 = blockIdx.x * 128;
    const __half* Pb = g_Ph + (size_t)b * NN * NN;
    const __half* Xb = g_xt + (size_t)b * DD * NN;
    int tid = threadIdx.x, wid = tid >> 5, lane = tid & 31;
    int wm = (wid & 3) * 32, wn = (wid >> 2) * 64;
    uint32_t sBase = smem_u32(dsm);

    delta_load_stage(sBase, Pb, Xb, q0, d0, tid, 0, 0);
    delta_load_stage(sBase, Pb, Xb, q0, d0, tid, 1, 64);

    float acc[2][8][4] = {};
    for (int c = 0; c < NN / 64; c++) {
        int s = c % 3;
        if (c < NN / 64 - 1) cp_wait<1>(); else cp_wait<0>();
        __syncthreads();
        if (c + 2 < NN / 64)
            delta_load_stage(sBase, Pb, Xb, q0, d0, tid, (c + 2) % 3, (c + 2) * 64);
        uint32_t aBase = sBase + (uint32_t)(s * 2) * DSTAGE * 2;
        uint32_t bBase = sBase + (uint32_t)(s * 2 + 1) * DSTAGE * 2;
#pragma unroll
        for (int kk = 0; kk < 64; kk += 16) {
            uint32_t a[2][4];
#pragma unroll
            for (int mf = 0; mf < 2; mf++) {
                int row = wm + mf * 16 + (lane & 15);
                ldsm_x4(a[mf][0], a[mf][1], a[mf][2], a[mf][3],
                        aBase + (uint32_t)(row * STR + kk + (lane >> 4) * 8) * 2);
            }
#pragma unroll
            for (int nf = 0; nf < 4; nf++) {
                int g = lane >> 3;
                int row = wn + nf * 16 + (lane & 7) + (g >> 1) * 8;
                uint32_t b0, b1, b2, b3;
                ldsm_x4(b0, b1, b2, b3,
                        bBase + (uint32_t)(row * STR + kk + (g & 1) * 8) * 2);
#pragma unroll
                for (int mf = 0; mf < 2; mf++) {
                    mma16816(acc[mf][nf * 2],     a[mf], b0, b1);
                    mma16816(acc[mf][nf * 2 + 1], a[mf], b2, b3);
                }
            }
        }
    }

    float* dp = g_delta + ((size_t)b * NN + q0) * DD + d0;
#pragma unroll
    for (int mf = 0; mf < 2; mf++) {
        int row = wm + mf * 16 + lane / 4;
        float il0 = 1.0f / g_L[b * NN + q0 + row];
        float il1 = 1.0f / g_L[b * NN + q0 + row + 8];
#pragma unroll
        for (int nf = 0; nf < 8; nf++) {
            int col = wn + nf * 8 + (lane & 3) * 2;
            *(float2*)&dp[(size_t)row * DD + col] =
                make_float2(acc[mf][nf][0] * il0, acc[mf][nf][1] * il0);
            *(float2*)&dp[(size_t)(row + 8) * DD + col] =
                make_float2(acc[mf][nf][2] * il1, acc[mf][nf][3] * il1);
        }
    }
}

// ---------------- out = LN(x + delta) ----------------------------------------
__global__ __launch_bounds__(256) void ln_kernel(
    const float* __restrict__ x, const float* __restrict__ gamma,
    const float* __restrict__ beta, float* __restrict__ out) {
    __shared__ float red[8];
    size_t token = blockIdx.x;
    const float* xr = x + token * DD;
    const float* dr = g_delta + token * DD;
    int tid = threadIdx.x;
    float4 xv = *(const float4*)(xr + tid * 4);
    float4 dv = *(const float4*)(dr + tid * 4);
    float y[4] = {xv.x + dv.x, xv.y + dv.y, xv.z + dv.z, xv.w + dv.w};
    float s = y[0] + y[1] + y[2] + y[3];
#pragma unroll
    for (int o = 16; o > 0; o >>= 1) s += __shfl_xor_sync(0xffffffffu, s, o);
    if ((tid & 31) == 0) red[tid >> 5] = s;
    __syncthreads();
    if (tid < 32) {
        float t = (tid < 8) ? red[tid] : 0.f;
#pragma unroll
        for (int o = 4; o > 0; o >>= 1) t += __shfl_xor_sync(0xffffffffu, t, o);
        if (tid == 0) red[0] = t;
    }
    __syncthreads();
    float mu = red[0] * (1.0f / DD);
    __syncthreads();
    float vs = 0.f;
#pragma unroll
    for (int i = 0; i < 4; i++) { float d = y[i] - mu; vs += d * d; }
#pragma unroll
    for (int o = 16; o > 0; o >>= 1) vs += __shfl_xor_sync(0xffffffffu, vs, o);
    if ((tid & 31) == 0) red[tid >> 5] = vs;
    __syncthreads();
    if (tid < 32) {
        float t = (tid < 8) ? red[tid] : 0.f;
#pragma unroll
        for (int o = 4; o > 0; o >>= 1) t += __shfl_xor_sync(0xffffffffu, t, o);
        if (tid == 0) red[0] = t;
    }
    __syncthreads();
    float inv = rsqrtf(red[0] * (1.0f / DD) + LN_EPS);
    float4 gv = *(const float4*)(gamma + tid * 4);
    float4 bv = *(const float4*)(beta + tid * 4);
    float4 o;
    o.x = (y[0] - mu) * inv * gv.x + bv.x;
    o.y = (y[1] - mu) * inv * gv.y + bv.y;
    o.z = (y[2] - mu) * inv * gv.z + bv.z;
    o.w = (y[3] - mu) * inv * gv.w + bv.w;
    *(float4*)(out + token * DD + tid * 4) = o;
}

extern "C" void kernel_launch(void* const* d_in, const int* in_sizes, int n_in,
                              void* d_out, int out_size) {
    const float* x     = (const float*)d_in[0];
    const float* mask  = (const float*)d_in[1];
    const float* U     = (const float*)d_in[2];
    const float* Vw    = (const float*)d_in[3];
    const float* gamma = (const float*)d_in[4];
    const float* beta  = (const float*)d_in[5];
    float* out = (float*)d_out;

    static bool attr_done = false;
    if (!attr_done) {
        cudaFuncSetAttribute(delta_mma_kernel,
                             cudaFuncAttributeMaxDynamicSharedMemorySize, DSMEM_BYTES);
        cudaFuncSetAttribute(proj_mma_kernel,
                             cudaFuncAttributeMaxDynamicSharedMemorySize, PSMEM_BYTES);
        attr_done = true;
    }

    reff_kernel<<<(NTOK + 255) / 256, 256>>>(mask);
    xt_kernel<<<dim3(NN / 32, DD / 32, BB), 256>>>(x);
    wt_kernel<<<dim3(DD / 32, RR / 32, 2), 256>>>(U, Vw);
    proj_mma_kernel<<<NTOK / 64, 256, PSMEM_BYTES>>>(mask);
    scores_mma_kernel<<<dim3(NN / 128, NN / 128, BB), 256>>>();
    delta_mma_kernel<<<dim3(DD / 128, NN / 128, BB), 256, DSMEM_BYTES>>>();
    ln_kernel<<<NTOK, 256>>>(x, gamma, beta, out);
}